// round 1
// baseline (speedup 1.0000x reference)
#include <cuda_runtime.h>

// Per-pixel dynamic conv (kernel-prediction network style), K=5.
// data: [B,C,H,W] f32; core: [B, K*K*C, H, W] f32 viewed as [B,K*K,C,H,W]
// out[b,c,h,w] = sum_t core[b,t,c,h,w] * data_pad[b,c,h + t/K - 2, w + t%K - 2]
//
// Shapes fixed by the problem: B=4, C=64, H=128, W=128, K=5.
// HBM-bound: core stream = 419 MB read-once; 1 thread = 1 float4 output.

#define KS 5
#define PAD 2

namespace {
constexpr int B = 4, C = 64, H = 128, W = 128;
constexpr int HW = H * W;
constexpr int CHW = C * HW;
constexpr int TAPS = KS * KS;
}

__global__ __launch_bounds__(256, 8)
void dynconv_kernel(const float* __restrict__ data,
                    const float* __restrict__ core,
                    float* __restrict__ out) {
    // Linear index over B*C*H*(W/4) float4 outputs = 1,048,576
    int idx = blockIdx.x * 256 + threadIdx.x;

    // W/4 = 32 (5 bits), H = 128 (7 bits), C = 64 (6 bits)
    int w4 = idx & 31;            // float4 column
    int h  = (idx >> 5) & (H - 1);
    int c  = (idx >> 12) & (C - 1);
    int b  = idx >> 18;
    int w0 = w4 << 2;             // first scalar column of this float4

    const float* dbase = data + ((long)(b * C + c)) * HW;          // [H,W] slice
    const float* cbase = core + ((long)(b * TAPS) * C + c) * HW + h * W + w0;

    float4 acc = make_float4(0.f, 0.f, 0.f, 0.f);

    #pragma unroll
    for (int di = 0; di < KS; di++) {
        int hh = h + di - PAD;
        // Load 8 data values covering w0-2 .. w0+5; taps dj reuse via register shift.
        float row[8];
        if (hh >= 0 && hh < H) {
            const float* dr = dbase + hh * W;
            #pragma unroll
            for (int k = 0; k < 8; k++) {
                int ww = w0 + k - PAD;
                row[k] = (ww >= 0 && ww < W) ? dr[ww] : 0.f;
            }
        } else {
            #pragma unroll
            for (int k = 0; k < 8; k++) row[k] = 0.f;
        }

        #pragma unroll
        for (int dj = 0; dj < KS; dj++) {
            int t = di * KS + dj;
            // core[b, t, c, h, w0..w0+3] — aligned, coalesced float4 stream
            float4 c4 = *reinterpret_cast<const float4*>(cbase + (long)t * CHW);
            // output column m uses data[w0 + m + dj - 2] = row[m + dj]
            acc.x += c4.x * row[dj + 0];
            acc.y += c4.y * row[dj + 1];
            acc.z += c4.z * row[dj + 2];
            acc.w += c4.w * row[dj + 3];
        }
    }

    *reinterpret_cast<float4*>(out + (long)idx * 4) = acc;
}

extern "C" void kernel_launch(void* const* d_in, const int* in_sizes, int n_in,
                              void* d_out, int out_size) {
    const float* data = (const float*)d_in[0];  // [4,64,128,128]
    const float* core = (const float*)d_in[1];  // [4,1600,128,128]
    float* out = (float*)d_out;                 // [4,64,128,128]

    int total4 = B * C * H * (W / 4);           // 1,048,576 float4 outputs
    int blocks = total4 / 256;                  // 4096
    dynconv_kernel<<<blocks, 256>>>(data, core, out);
}

// round 2
// speedup vs baseline: 1.1320x; 1.1320x over previous
#include <cuda_runtime.h>

// Per-pixel dynamic conv (KPN style), K=5.
// out[b,c,h,w] = sum_t core[b,t,c,h,w] * data_pad[b,c,h + t/5 - 2, w + t%5 - 2]
// B=4, C=64, H=128, W=128. Pure HBM-stream: core = 419 MB read-once.
//
// R2 change vs R1 (72.4us, DRAM 81.3%, regs=32):
//  - relax launch bounds (32 -> ~64 regs) so each di-row's 5 core LDG.128
//    issue back-to-back => higher MLP_eff, fewer DRAM idle cycles
//  - __ldcs on core (streaming, evict-first), __ldg on data (L2-resident)

#define KS 5
#define PAD 2

namespace {
constexpr int B = 4, C = 64, H = 128, W = 128;
constexpr int HW = H * W;
constexpr int CHW = C * HW;
constexpr int TAPS = KS * KS;
}

__global__ __launch_bounds__(256, 4)
void dynconv_kernel(const float* __restrict__ data,
                    const float* __restrict__ core,
                    float* __restrict__ out) {
    int idx = blockIdx.x * 256 + threadIdx.x;

    // W/4 = 32 (5 bits), H = 128 (7 bits), C = 64 (6 bits)
    int w4 = idx & 31;
    int h  = (idx >> 5) & (H - 1);
    int c  = (idx >> 12) & (C - 1);
    int b  = idx >> 18;
    int w0 = w4 << 2;

    const float* dbase = data + ((long)(b * C + c)) * HW;
    const float* cbase = core + ((long)(b * TAPS) * C + c) * HW + h * W + w0;

    float4 acc = make_float4(0.f, 0.f, 0.f, 0.f);

    #pragma unroll
    for (int di = 0; di < KS; di++) {
        int hh = h + di - PAD;

        // ---- front-batch: 5 streaming core loads (independent, back-to-back) ----
        const float4* cb = reinterpret_cast<const float4*>(cbase + (long)(di * KS) * CHW);
        float4 c0 = __ldcs(cb);
        cb = reinterpret_cast<const float4*>(reinterpret_cast<const char*>(cb) + (long)CHW * 4);
        float4 c1 = __ldcs(cb);
        cb = reinterpret_cast<const float4*>(reinterpret_cast<const char*>(cb) + (long)CHW * 4);
        float4 c2 = __ldcs(cb);
        cb = reinterpret_cast<const float4*>(reinterpret_cast<const char*>(cb) + (long)CHW * 4);
        float4 c3 = __ldcs(cb);
        cb = reinterpret_cast<const float4*>(reinterpret_cast<const char*>(cb) + (long)CHW * 4);
        float4 c4 = __ldcs(cb);

        // ---- data row (L1/L2 hits): 8 values w0-2 .. w0+5 ----
        float row[8];
        if (hh >= 0 && hh < H) {
            const float* dr = dbase + hh * W;
            #pragma unroll
            for (int k = 0; k < 8; k++) {
                int ww = w0 + k - PAD;
                row[k] = (ww >= 0 && ww < W) ? __ldg(dr + ww) : 0.f;
            }
        } else {
            #pragma unroll
            for (int k = 0; k < 8; k++) row[k] = 0.f;
        }

        // ---- consume: output col m of tap dj uses row[m + dj] ----
        acc.x += c0.x * row[0]; acc.y += c0.y * row[1]; acc.z += c0.z * row[2]; acc.w += c0.w * row[3];
        acc.x += c1.x * row[1]; acc.y += c1.y * row[2]; acc.z += c1.z * row[3]; acc.w += c1.w * row[4];
        acc.x += c2.x * row[2]; acc.y += c2.y * row[3]; acc.z += c2.z * row[4]; acc.w += c2.w * row[5];
        acc.x += c3.x * row[3]; acc.y += c3.y * row[4]; acc.z += c3.z * row[5]; acc.w += c3.w * row[6];
        acc.x += c4.x * row[4]; acc.y += c4.y * row[5]; acc.z += c4.z * row[6]; acc.w += c4.w * row[7];
    }

    *reinterpret_cast<float4*>(out + (long)idx * 4) = acc;
}

extern "C" void kernel_launch(void* const* d_in, const int* in_sizes, int n_in,
                              void* d_out, int out_size) {
    const float* data = (const float*)d_in[0];  // [4,64,128,128]
    const float* core = (const float*)d_in[1];  // [4,1600,128,128]
    float* out = (float*)d_out;                 // [4,64,128,128]

    int total4 = B * C * H * (W / 4);           // 1,048,576
    dynconv_kernel<<<total4 / 256, 256>>>(data, core, out);
}